// round 5
// baseline (speedup 1.0000x reference)
#include <cuda_runtime.h>
#include <math.h>
#include <stdint.h>

// ---------------------------------------------------------------------------
// Problem constants
// ---------------------------------------------------------------------------
#define BATCH 2048
#define SEQ   15
#define CH    1024
#define NH    16
#define HSZ   64
#define MROWS (BATCH * SEQ)          // 30720
#define SCALE 0.125f                 // 64^-0.5
#define LN_EPS 1e-5f

// ---------------------------------------------------------------------------
// Scratch (static __device__ — no allocations allowed)
// ---------------------------------------------------------------------------
__device__ float g_xj   [(size_t)MROWS * CH];
__device__ float g_xi   [(size_t)MROWS * CH];
__device__ float g_Jqkv [(size_t)MROWS * 3 * CH];
__device__ float g_Iqkv [(size_t)MROWS * 3 * CH];
__device__ float g_attnX[(size_t)MROWS * CH];
__device__ float g_joint[(size_t)MROWS * CH];
__device__ float g_ynorm[(size_t)MROWS * CH];
__device__ float g_hmid [(size_t)MROWS * (CH / 2)];

// ---------------------------------------------------------------------------
// Helpers
// ---------------------------------------------------------------------------
__device__ __forceinline__ float f2tf32(float x) {
    unsigned u;
    asm("cvt.rna.tf32.f32 %0, %1;" : "=r"(u) : "f"(x));
    return __uint_as_float(u);
}

__device__ __forceinline__ void mma_tf32(float* c, const unsigned* a, const unsigned* b) {
    asm volatile(
        "mma.sync.aligned.m16n8k8.row.col.f32.tf32.tf32.f32 "
        "{%0,%1,%2,%3}, {%4,%5,%6,%7}, {%8,%9}, {%0,%1,%2,%3};\n"
        : "+f"(c[0]), "+f"(c[1]), "+f"(c[2]), "+f"(c[3])
        : "r"(a[0]), "r"(a[1]), "r"(a[2]), "r"(a[3]), "r"(b[0]), "r"(b[1]));
}

// ---------------------------------------------------------------------------
// LayerNorm: one block (256 thr) per row of 1024
// ---------------------------------------------------------------------------
__global__ void ln_kernel(const float* __restrict__ x,
                          const float* __restrict__ g,
                          const float* __restrict__ b,
                          float* __restrict__ out) {
    const int row = blockIdx.x;
    const int t = threadIdx.x;
    const float4* xr = (const float4*)(x + (size_t)row * CH);
    float4 v = xr[t];
    float s1 = v.x + v.y + v.z + v.w;
    float s2 = v.x * v.x + v.y * v.y + v.z * v.z + v.w * v.w;
    #pragma unroll
    for (int o = 16; o; o >>= 1) {
        s1 += __shfl_xor_sync(0xffffffffu, s1, o);
        s2 += __shfl_xor_sync(0xffffffffu, s2, o);
    }
    __shared__ float w1[8], w2[8];
    if ((t & 31) == 0) { w1[t >> 5] = s1; w2[t >> 5] = s2; }
    __syncthreads();
    if (t < 32) {
        s1 = (t < 8) ? w1[t] : 0.0f;
        s2 = (t < 8) ? w2[t] : 0.0f;
        #pragma unroll
        for (int o = 4; o; o >>= 1) {
            s1 += __shfl_xor_sync(0xffffffffu, s1, o);
            s2 += __shfl_xor_sync(0xffffffffu, s2, o);
        }
        if (t == 0) { w1[0] = s1; w2[0] = s2; }
    }
    __syncthreads();
    const float m = w1[0] * (1.0f / CH);
    const float var = w2[0] * (1.0f / CH) - m * m;
    const float r = rsqrtf(var + LN_EPS);
    float4 gv = ((const float4*)g)[t];
    float4 bv = ((const float4*)b)[t];
    float4 o;
    o.x = (v.x - m) * r * gv.x + bv.x;
    o.y = (v.y - m) * r * gv.y + bv.y;
    o.z = (v.z - m) * r * gv.z + bv.z;
    o.w = (v.w - m) * r * gv.w + bv.w;
    ((float4*)(out + (size_t)row * CH))[t] = o;
}

// ---------------------------------------------------------------------------
// tf32 GEMM: C[M x Ncols] = A[M x K] * B[K x Ncols] (+epilogue)
// 128x128x16 blocktile, double-buffered, 256 threads, 2x4 warp grid.
// EPI: 0 = plain store, 1 = +bias +resid, 2 = +bias then exact GELU
// ---------------------------------------------------------------------------
#define BM 128
#define BN 128
#define BK 16
#define ASTRIDE (BK + 4)     // 20: conflict-free for A-frag loads
#define BSTRIDE (BN + 8)     // 136: conflict-free for B-frag loads

template <int EPI>
__global__ __launch_bounds__(256)
void gemm_tf32(const float* __restrict__ A, const float* __restrict__ B,
               float* __restrict__ C, int Ncols, int K,
               const float* __restrict__ bias, const float* __restrict__ resid) {
    __shared__ float sA[2][BM][ASTRIDE];
    __shared__ float sB[2][BK][BSTRIDE];

    const int tid  = threadIdx.x;
    const int warp = tid >> 5;
    const int lane = tid & 31;
    const int g = lane >> 2;          // 0..7
    const int t = lane & 3;           // 0..3
    const int wm = (warp >> 2) * 64;  // warp m-base: 0 or 64
    const int wn = (warp & 3) * 32;   // warp n-base: 0,32,64,96

    const int bm = blockIdx.y * BM;
    const int bn = blockIdx.x * BN;

    const float* Abase = A + (size_t)bm * K;
    const float* Bbase = B + bn;

    float acc[4][4][4];
    #pragma unroll
    for (int i = 0; i < 4; i++)
        #pragma unroll
        for (int j = 0; j < 4; j++)
            #pragma unroll
            for (int e = 0; e < 4; e++) acc[i][j][e] = 0.0f;

    // gmem staging registers
    float4 ra[2], rb[2];

    const int a_r0 = tid >> 2,          a_c0 = (tid & 3) << 2;
    const int a_r1 = (tid + 256) >> 2,  a_c1 = ((tid + 256) & 3) << 2;
    const int b_r0 = tid >> 5,          b_c0 = (tid & 31) << 2;
    const int b_r1 = (tid + 256) >> 5,  b_c1 = ((tid + 256) & 31) << 2;

    const int nkt = K / BK;

    // prologue loads (kt = 0)
    ra[0] = *(const float4*)(Abase + (size_t)a_r0 * K + a_c0);
    ra[1] = *(const float4*)(Abase + (size_t)a_r1 * K + a_c1);
    rb[0] = *(const float4*)(Bbase + (size_t)b_r0 * Ncols + b_c0);
    rb[1] = *(const float4*)(Bbase + (size_t)b_r1 * Ncols + b_c1);

    {
        float4 v;
        v = ra[0]; v.x=f2tf32(v.x); v.y=f2tf32(v.y); v.z=f2tf32(v.z); v.w=f2tf32(v.w);
        *(float4*)&sA[0][a_r0][a_c0] = v;
        v = ra[1]; v.x=f2tf32(v.x); v.y=f2tf32(v.y); v.z=f2tf32(v.z); v.w=f2tf32(v.w);
        *(float4*)&sA[0][a_r1][a_c1] = v;
        v = rb[0]; v.x=f2tf32(v.x); v.y=f2tf32(v.y); v.z=f2tf32(v.z); v.w=f2tf32(v.w);
        *(float4*)&sB[0][b_r0][b_c0] = v;
        v = rb[1]; v.x=f2tf32(v.x); v.y=f2tf32(v.y); v.z=f2tf32(v.z); v.w=f2tf32(v.w);
        *(float4*)&sB[0][b_r1][b_c1] = v;
    }
    __syncthreads();

    for (int kt = 0; kt < nkt; kt++) {
        const int cur = kt & 1;
        if (kt + 1 < nkt) {
            const int ko = (kt + 1) * BK;
            ra[0] = *(const float4*)(Abase + (size_t)a_r0 * K + ko + a_c0);
            ra[1] = *(const float4*)(Abase + (size_t)a_r1 * K + ko + a_c1);
            rb[0] = *(const float4*)(Bbase + (size_t)(ko + b_r0) * Ncols + b_c0);
            rb[1] = *(const float4*)(Bbase + (size_t)(ko + b_r1) * Ncols + b_c1);
        }

        #pragma unroll
        for (int ks = 0; ks < 2; ks++) {
            const int k0 = ks * 8;
            unsigned af[4][4], bf[4][2];
            #pragma unroll
            for (int mi = 0; mi < 4; mi++) {
                const int r = wm + mi * 16 + g;
                af[mi][0] = __float_as_uint(sA[cur][r    ][k0 + t]);
                af[mi][1] = __float_as_uint(sA[cur][r + 8][k0 + t]);
                af[mi][2] = __float_as_uint(sA[cur][r    ][k0 + t + 4]);
                af[mi][3] = __float_as_uint(sA[cur][r + 8][k0 + t + 4]);
            }
            #pragma unroll
            for (int ni = 0; ni < 4; ni++) {
                const int c = wn + ni * 8 + g;
                bf[ni][0] = __float_as_uint(sB[cur][k0 + t    ][c]);
                bf[ni][1] = __float_as_uint(sB[cur][k0 + t + 4][c]);
            }
            #pragma unroll
            for (int mi = 0; mi < 4; mi++)
                #pragma unroll
                for (int ni = 0; ni < 4; ni++)
                    mma_tf32(acc[mi][ni], af[mi], bf[ni]);
        }

        if (kt + 1 < nkt) {
            const int nxt = (kt + 1) & 1;
            float4 v;
            v = ra[0]; v.x=f2tf32(v.x); v.y=f2tf32(v.y); v.z=f2tf32(v.z); v.w=f2tf32(v.w);
            *(float4*)&sA[nxt][a_r0][a_c0] = v;
            v = ra[1]; v.x=f2tf32(v.x); v.y=f2tf32(v.y); v.z=f2tf32(v.z); v.w=f2tf32(v.w);
            *(float4*)&sA[nxt][a_r1][a_c1] = v;
            v = rb[0]; v.x=f2tf32(v.x); v.y=f2tf32(v.y); v.z=f2tf32(v.z); v.w=f2tf32(v.w);
            *(float4*)&sB[nxt][b_r0][b_c0] = v;
            v = rb[1]; v.x=f2tf32(v.x); v.y=f2tf32(v.y); v.z=f2tf32(v.z); v.w=f2tf32(v.w);
            *(float4*)&sB[nxt][b_r1][b_c1] = v;
        }
        __syncthreads();
    }

    // epilogue
    #pragma unroll
    for (int mi = 0; mi < 4; mi++) {
        #pragma unroll
        for (int ni = 0; ni < 4; ni++) {
            const int r0 = bm + wm + mi * 16 + g;
            const int c0 = bn + wn + ni * 8 + t * 2;
            float v[4] = {acc[mi][ni][0], acc[mi][ni][1], acc[mi][ni][2], acc[mi][ni][3]};
            const int rr[4] = {r0, r0, r0 + 8, r0 + 8};
            const int cc[4] = {c0, c0 + 1, c0, c0 + 1};
            if (EPI != 0) {
                #pragma unroll
                for (int e = 0; e < 4; e++) {
                    v[e] += bias[cc[e]];
                    if (EPI == 1) v[e] += resid[(size_t)rr[e] * Ncols + cc[e]];
                    if (EPI == 2) v[e] = 0.5f * v[e] * (1.0f + erff(v[e] * 0.70710678118654752f));
                }
            }
            float2 lo = make_float2(v[0], v[1]);
            float2 hi = make_float2(v[2], v[3]);
            *(float2*)&C[(size_t)r0       * Ncols + c0] = lo;
            *(float2*)&C[(size_t)(r0 + 8) * Ncols + c0] = hi;
        }
    }
}

// ---------------------------------------------------------------------------
// Attention: one block (128 thr) per (batch, head)
// scores = (Jq.Jk^T + Iq.Ik^T + Iv @ W_Iconv) * SCALE ; softmax ; @ Jv
// ---------------------------------------------------------------------------
__global__ __launch_bounds__(128)
void attn_kernel(const float* __restrict__ Jqkv, const float* __restrict__ Iqkv,
                 const float* __restrict__ Wc, float* __restrict__ outX) {
    const int bh = blockIdx.x;
    const int b = bh >> 4;
    const int h = bh & 15;
    const int tid = threadIdx.x;

    __shared__ float sJq[SEQ][HSZ + 1], sJk[SEQ][HSZ + 1], sJv[SEQ][HSZ + 1];
    __shared__ float sIq[SEQ][HSZ + 1], sIk[SEQ][HSZ + 1], sIv[SEQ][HSZ + 1];
    __shared__ float sW[HSZ][SEQ];
    __shared__ float sS[SEQ][SEQ + 1];

    const size_t base = (size_t)b * SEQ * (3 * CH) + (size_t)h * HSZ;
    for (int i = tid; i < SEQ * HSZ; i += 128) {
        const int n = i >> 6, d = i & 63;
        const float* jp = Jqkv + base + (size_t)n * (3 * CH) + d;
        sJq[n][d] = jp[0];
        sJk[n][d] = jp[CH];
        sJv[n][d] = jp[2 * CH];
        const float* ip = Iqkv + base + (size_t)n * (3 * CH) + d;
        sIq[n][d] = ip[0];
        sIk[n][d] = ip[CH];
        sIv[n][d] = ip[2 * CH];
    }
    for (int i = tid; i < HSZ * SEQ; i += 128) sW[i / SEQ][i % SEQ] = Wc[i];
    __syncthreads();

    // FIX (R2): 225 score entries but only 128 threads -> must stride.
    for (int i = tid; i < SEQ * SEQ; i += 128) {
        const int q = i / SEQ, k = i % SEQ;
        float acc = 0.0f, accl = 0.0f;
        #pragma unroll
        for (int d = 0; d < HSZ; d++) {
            acc  += sJq[q][d] * sJk[k][d] + sIq[q][d] * sIk[k][d];
            accl += sIv[q][d] * sW[d][k];
        }
        sS[q][k] = (acc + accl) * SCALE;
    }
    __syncthreads();

    if (tid < SEQ) {
        const int q = tid;
        float mx = -1e30f;
        #pragma unroll
        for (int k = 0; k < SEQ; k++) mx = fmaxf(mx, sS[q][k]);
        float sum = 0.0f;
        #pragma unroll
        for (int k = 0; k < SEQ; k++) { float e = expf(sS[q][k] - mx); sS[q][k] = e; sum += e; }
        const float inv = 1.0f / sum;
        #pragma unroll
        for (int k = 0; k < SEQ; k++) sS[q][k] *= inv;
    }
    __syncthreads();

    for (int i = tid; i < SEQ * HSZ; i += 128) {
        const int q = i >> 6, d = i & 63;
        float acc = 0.0f;
        #pragma unroll
        for (int k = 0; k < SEQ; k++) acc += sS[q][k] * sJv[k][d];
        outX[((size_t)b * SEQ + q) * CH + (size_t)h * HSZ + d] = acc;
    }
}

// ---------------------------------------------------------------------------
// Host entry
// ---------------------------------------------------------------------------
extern "C" void kernel_launch(void* const* d_in, const int* in_sizes, int n_in,
                              void* d_out, int out_size) {
    const float* joint_feature    = (const float*)d_in[0];
    const float* relation_feature = (const float*)d_in[1];
    const float* W_Jqkv  = (const float*)d_in[2];
    const float* W_Iqk   = (const float*)d_in[3];
    const float* W_Iconv = (const float*)d_in[4];
    const float* W_proj  = (const float*)d_in[5];
    const float* b_proj  = (const float*)d_in[6];
    const float* g_attn1 = (const float*)d_in[7];
    const float* b_attn1 = (const float*)d_in[8];
    const float* g_attn2 = (const float*)d_in[9];
    const float* b_attn2 = (const float*)d_in[10];
    const float* g_jln   = (const float*)d_in[11];
    const float* b_jln   = (const float*)d_in[12];
    const float* W_fc1   = (const float*)d_in[13];
    const float* b_fc1   = (const float*)d_in[14];
    const float* W_fc2   = (const float*)d_in[15];
    const float* b_fc2   = (const float*)d_in[16];
    float* out = (float*)d_out;

    float *xj, *xi, *Jq, *Iq, *ax, *jt, *yn, *hm;
    cudaGetSymbolAddress((void**)&xj, g_xj);
    cudaGetSymbolAddress((void**)&xi, g_xi);
    cudaGetSymbolAddress((void**)&Jq, g_Jqkv);
    cudaGetSymbolAddress((void**)&Iq, g_Iqkv);
    cudaGetSymbolAddress((void**)&ax, g_attnX);
    cudaGetSymbolAddress((void**)&jt, g_joint);
    cudaGetSymbolAddress((void**)&yn, g_ynorm);
    cudaGetSymbolAddress((void**)&hm, g_hmid);

    // 1) LN both streams
    ln_kernel<<<MROWS, 256>>>(joint_feature,    g_attn1, b_attn1, xj);
    ln_kernel<<<MROWS, 256>>>(relation_feature, g_attn2, b_attn2, xi);

    // 2) QKV projections
    {
        dim3 grid(3 * CH / BN, MROWS / BM);
        gemm_tf32<0><<<grid, 256>>>(xj, W_Jqkv, Jq, 3 * CH, CH, nullptr, nullptr);
        gemm_tf32<0><<<grid, 256>>>(xi, W_Iqk,  Iq, 3 * CH, CH, nullptr, nullptr);
    }

    // 3) Attention
    attn_kernel<<<BATCH * NH, 128>>>(Jq, Iq, W_Iconv, ax);

    // 4) Projection + bias + residual -> joint
    {
        dim3 grid(CH / BN, MROWS / BM);
        gemm_tf32<1><<<grid, 256>>>(ax, W_proj, jt, CH, CH, b_proj, joint_feature);
    }

    // 5) LN(joint)
    ln_kernel<<<MROWS, 256>>>(jt, g_jln, b_jln, yn);

    // 6) fc1 + bias + GELU
    {
        dim3 grid((CH / 2) / BN, MROWS / BM);
        gemm_tf32<2><<<grid, 256>>>(yn, W_fc1, hm, CH / 2, CH, b_fc1, nullptr);
    }

    // 7) fc2 + bias + residual(joint) -> out
    {
        dim3 grid(CH / BN, MROWS / BM);
        gemm_tf32<1><<<grid, 256>>>(hm, W_fc2, out, CH, CH / 2, b_fc2, jt);
    }
}

// round 9
// speedup vs baseline: 1.1823x; 1.1823x over previous
#include <cuda_runtime.h>
#include <math.h>
#include <stdint.h>

// ---------------------------------------------------------------------------
// Problem constants
// ---------------------------------------------------------------------------
#define BATCH 2048
#define SEQ   15
#define CH    1024
#define NH    16
#define HSZ   64
#define MROWS (BATCH * SEQ)          // 30720
#define SCALE 0.125f
#define LN_EPS 1e-5f

// ---------------------------------------------------------------------------
// Scratch (static __device__ — no allocations allowed)
// ---------------------------------------------------------------------------
__device__ float g_xj   [(size_t)MROWS * CH];
__device__ float g_xi   [(size_t)MROWS * CH];
__device__ float g_Jqkv [(size_t)MROWS * 3 * CH];
__device__ float g_Iqkv [(size_t)MROWS * 3 * CH];
__device__ float g_attnX[(size_t)MROWS * CH];
__device__ float g_joint[(size_t)MROWS * CH];
__device__ float g_ynorm[(size_t)MROWS * CH];
__device__ float g_hmid [(size_t)MROWS * (CH / 2)];

// ---------------------------------------------------------------------------
// Helpers
// ---------------------------------------------------------------------------
__device__ __forceinline__ float f2tf32(float x) {
    unsigned u;
    asm("cvt.rna.tf32.f32 %0, %1;" : "=r"(u) : "f"(x));
    return __uint_as_float(u);
}
__device__ __forceinline__ float4 f2tf32_4(float4 v) {
    v.x = f2tf32(v.x); v.y = f2tf32(v.y); v.z = f2tf32(v.z); v.w = f2tf32(v.w);
    return v;
}
__device__ __forceinline__ void mma_tf32(float* c, const unsigned* a, const unsigned* b) {
    asm volatile(
        "mma.sync.aligned.m16n8k8.row.col.f32.tf32.tf32.f32 "
        "{%0,%1,%2,%3}, {%4,%5,%6,%7}, {%8,%9}, {%0,%1,%2,%3};\n"
        : "+f"(c[0]), "+f"(c[1]), "+f"(c[2]), "+f"(c[3])
        : "r"(a[0]), "r"(a[1]), "r"(a[2]), "r"(a[3]), "r"(b[0]), "r"(b[1]));
}
__device__ __forceinline__ unsigned smem_addr_u32(const void* p) {
    return (unsigned)__cvta_generic_to_shared(p);
}
__device__ __forceinline__ void cp_async16(unsigned s, const void* g) {
    asm volatile("cp.async.cg.shared.global [%0], [%1], 16;" :: "r"(s), "l"(g) : "memory");
}
__device__ __forceinline__ void cp_commit() {
    asm volatile("cp.async.commit_group;" ::: "memory");
}
template <int N>
__device__ __forceinline__ void cp_wait() {
    asm volatile("cp.async.wait_group %0;" :: "n"(N) : "memory");
}

// ---------------------------------------------------------------------------
// LayerNorm: one block (256 thr) per row of 1024. Output pre-rounded to tf32
// (every consumer of LN output is a GEMM A-operand).
// ---------------------------------------------------------------------------
__global__ void ln_kernel(const float* __restrict__ x,
                          const float* __restrict__ g,
                          const float* __restrict__ b,
                          float* __restrict__ out) {
    const int row = blockIdx.x;
    const int t = threadIdx.x;
    const float4* xr = (const float4*)(x + (size_t)row * CH);
    float4 v = xr[t];
    float s1 = v.x + v.y + v.z + v.w;
    float s2 = v.x * v.x + v.y * v.y + v.z * v.z + v.w * v.w;
    #pragma unroll
    for (int o = 16; o; o >>= 1) {
        s1 += __shfl_xor_sync(0xffffffffu, s1, o);
        s2 += __shfl_xor_sync(0xffffffffu, s2, o);
    }
    __shared__ float w1[8], w2[8];
    if ((t & 31) == 0) { w1[t >> 5] = s1; w2[t >> 5] = s2; }
    __syncthreads();
    if (t < 32) {
        s1 = (t < 8) ? w1[t] : 0.0f;
        s2 = (t < 8) ? w2[t] : 0.0f;
        #pragma unroll
        for (int o = 4; o; o >>= 1) {
            s1 += __shfl_xor_sync(0xffffffffu, s1, o);
            s2 += __shfl_xor_sync(0xffffffffu, s2, o);
        }
        if (t == 0) { w1[0] = s1; w2[0] = s2; }
    }
    __syncthreads();
    const float m = w1[0] * (1.0f / CH);
    const float var = w2[0] * (1.0f / CH) - m * m;
    const float r = rsqrtf(var + LN_EPS);
    float4 gv = ((const float4*)g)[t];
    float4 bv = ((const float4*)b)[t];
    float4 o;
    o.x = (v.x - m) * r * gv.x + bv.x;
    o.y = (v.y - m) * r * gv.y + bv.y;
    o.z = (v.z - m) * r * gv.z + bv.z;
    o.w = (v.w - m) * r * gv.w + bv.w;
    ((float4*)(out + (size_t)row * CH))[t] = f2tf32_4(o);
}

// ---------------------------------------------------------------------------
// tf32 GEMM: C[M x Ncols] = A[M x K] * B[K x Ncols] (+epilogue)
// 128x128x16 blocktile, 3-stage cp.async pipeline, 256 threads, 2x4 warps.
// A and B are assumed PRE-ROUNDED to tf32 by their producers.
// EPI: 0 = plain store, 1 = +bias +resid, 2 = +bias then exact GELU (tf32 out)
// ---------------------------------------------------------------------------
#define BM 128
#define BN 128
#define BK 16
#define ASTRIDE (BK + 4)     // 20
#define BSTRIDE (BN + 8)     // 136
#define STAGE_F (BM * ASTRIDE + BK * BSTRIDE)   // 2560 + 2176 = 4736 floats
#define NSTAGE 3
#define GEMM_SMEM (NSTAGE * STAGE_F * 4)        // 56832 bytes

template <int EPI>
__global__ __launch_bounds__(256, 2)
void gemm_tf32(const float* __restrict__ A, const float* __restrict__ B,
               float* __restrict__ C, int Ncols, int K,
               const float* __restrict__ bias, const float* __restrict__ resid) {
    extern __shared__ float smem[];

    const int tid  = threadIdx.x;
    const int warp = tid >> 5;
    const int lane = tid & 31;
    const int g = lane >> 2;          // 0..7
    const int t = lane & 3;           // 0..3
    const int wm = (warp >> 2) * 64;
    const int wn = (warp & 3) * 32;

    const int bm = blockIdx.y * BM;
    const int bn = blockIdx.x * BN;

    const float* Abase = A + (size_t)bm * K;
    const float* Bbase = B + bn;

    float acc[4][4][4];
    #pragma unroll
    for (int i = 0; i < 4; i++)
        #pragma unroll
        for (int j = 0; j < 4; j++)
            #pragma unroll
            for (int e = 0; e < 4; e++) acc[i][j][e] = 0.0f;

    const int nkt = K / BK;

    // per-thread load slots: A tile = 512 float4 chunks, B tile = 512 chunks
    // A chunk c: row=c>>2, c4=(c&3)*4 ; B chunk c: row=c>>5, col=(c&31)*4
    const int a_r0 = tid >> 2,          a_c0 = (tid & 3) << 2;
    const int a_r1 = (tid + 256) >> 2,  a_c1 = ((tid + 256) & 3) << 2;
    const int b_r0 = tid >> 5,          b_c0 = (tid & 31) << 2;
    const int b_r1 = (tid + 256) >> 5,  b_c1 = ((tid + 256) & 31) << 2;

    // stage load: issue 4 cp.async per thread
    auto load_stage = [&](int slot, int kt) {
        float* st = smem + slot * STAGE_F;
        float* sB = st + BM * ASTRIDE;
        const int kf = kt * BK;
        cp_async16(smem_addr_u32(st + a_r0 * ASTRIDE + a_c0),
                   Abase + (size_t)a_r0 * K + kf + a_c0);
        cp_async16(smem_addr_u32(st + a_r1 * ASTRIDE + a_c1),
                   Abase + (size_t)a_r1 * K + kf + a_c1);
        cp_async16(smem_addr_u32(sB + b_r0 * BSTRIDE + b_c0),
                   Bbase + (size_t)(kf + b_r0) * Ncols + b_c0);
        cp_async16(smem_addr_u32(sB + b_r1 * BSTRIDE + b_c1),
                   Bbase + (size_t)(kf + b_r1) * Ncols + b_c1);
    };

    // prologue: stages 0,1
    load_stage(0, 0); cp_commit();
    if (nkt > 1) load_stage(1, 1);
    cp_commit();

    for (int kt = 0; kt < nkt; kt++) {
        if (kt + 2 < nkt) load_stage((kt + 2) % NSTAGE, kt + 2);
        cp_commit();
        cp_wait<2>();            // stage kt complete
        __syncthreads();

        const float* st = smem + (kt % NSTAGE) * STAGE_F;
        const float* sB = st + BM * ASTRIDE;

        #pragma unroll
        for (int ks = 0; ks < 2; ks++) {
            const int k0 = ks * 8;
            unsigned af[4][4], bf[4][2];
            #pragma unroll
            for (int mi = 0; mi < 4; mi++) {
                const int r = wm + mi * 16 + g;
                af[mi][0] = __float_as_uint(st[(r    ) * ASTRIDE + k0 + t]);
                af[mi][1] = __float_as_uint(st[(r + 8) * ASTRIDE + k0 + t]);
                af[mi][2] = __float_as_uint(st[(r    ) * ASTRIDE + k0 + t + 4]);
                af[mi][3] = __float_as_uint(st[(r + 8) * ASTRIDE + k0 + t + 4]);
            }
            #pragma unroll
            for (int ni = 0; ni < 4; ni++) {
                const int c = wn + ni * 8 + g;
                bf[ni][0] = __float_as_uint(sB[(k0 + t    ) * BSTRIDE + c]);
                bf[ni][1] = __float_as_uint(sB[(k0 + t + 4) * BSTRIDE + c]);
            }
            #pragma unroll
            for (int mi = 0; mi < 4; mi++)
                #pragma unroll
                for (int ni = 0; ni < 4; ni++)
                    mma_tf32(acc[mi][ni], af[mi], bf[ni]);
        }
        __syncthreads();         // protect slot (kt%NSTAGE) before next-iter load
    }

    // epilogue
    #pragma unroll
    for (int mi = 0; mi < 4; mi++) {
        #pragma unroll
        for (int ni = 0; ni < 4; ni++) {
            const int r0 = bm + wm + mi * 16 + g;
            const int c0 = bn + wn + ni * 8 + t * 2;
            float v[4] = {acc[mi][ni][0], acc[mi][ni][1], acc[mi][ni][2], acc[mi][ni][3]};
            const int rr[4] = {r0, r0, r0 + 8, r0 + 8};
            const int cc[4] = {c0, c0 + 1, c0, c0 + 1};
            if (EPI != 0) {
                #pragma unroll
                for (int e = 0; e < 4; e++) {
                    v[e] += bias[cc[e]];
                    if (EPI == 1) v[e] += resid[(size_t)rr[e] * Ncols + cc[e]];
                    if (EPI == 2) {
                        v[e] = 0.5f * v[e] * (1.0f + erff(v[e] * 0.70710678118654752f));
                        v[e] = f2tf32(v[e]);   // hm feeds fc2 as A-operand
                    }
                }
            }
            float2 lo = make_float2(v[0], v[1]);
            float2 hi = make_float2(v[2], v[3]);
            *(float2*)&C[(size_t)r0       * Ncols + c0] = lo;
            *(float2*)&C[(size_t)(r0 + 8) * Ncols + c0] = hi;
        }
    }
}

// ---------------------------------------------------------------------------
// Attention: one block (128 thr) per (batch, head). Output pre-rounded tf32
// (it is the A-operand of the proj GEMM).
// ---------------------------------------------------------------------------
__global__ __launch_bounds__(128)
void attn_kernel(const float* __restrict__ Jqkv, const float* __restrict__ Iqkv,
                 const float* __restrict__ Wc, float* __restrict__ outX) {
    const int bh = blockIdx.x;
    const int b = bh >> 4;
    const int h = bh & 15;
    const int tid = threadIdx.x;

    __shared__ float sJq[SEQ][HSZ + 1], sJk[SEQ][HSZ + 1], sJv[SEQ][HSZ + 1];
    __shared__ float sIq[SEQ][HSZ + 1], sIk[SEQ][HSZ + 1], sIv[SEQ][HSZ + 1];
    __shared__ float sW[HSZ][SEQ];
    __shared__ float sS[SEQ][SEQ + 1];

    const size_t base = (size_t)b * SEQ * (3 * CH) + (size_t)h * HSZ;
    for (int i = tid; i < SEQ * HSZ; i += 128) {
        const int n = i >> 6, d = i & 63;
        const float* jp = Jqkv + base + (size_t)n * (3 * CH) + d;
        sJq[n][d] = jp[0];
        sJk[n][d] = jp[CH];
        sJv[n][d] = jp[2 * CH];
        const float* ip = Iqkv + base + (size_t)n * (3 * CH) + d;
        sIq[n][d] = ip[0];
        sIk[n][d] = ip[CH];
        sIv[n][d] = ip[2 * CH];
    }
    for (int i = tid; i < HSZ * SEQ; i += 128) sW[i / SEQ][i % SEQ] = Wc[i];
    __syncthreads();

    for (int i = tid; i < SEQ * SEQ; i += 128) {
        const int q = i / SEQ, k = i % SEQ;
        float acc = 0.0f, accl = 0.0f;
        #pragma unroll
        for (int d = 0; d < HSZ; d++) {
            acc  += sJq[q][d] * sJk[k][d] + sIq[q][d] * sIk[k][d];
            accl += sIv[q][d] * sW[d][k];
        }
        sS[q][k] = (acc + accl) * SCALE;
    }
    __syncthreads();

    if (tid < SEQ) {
        const int q = tid;
        float mx = -1e30f;
        #pragma unroll
        for (int k = 0; k < SEQ; k++) mx = fmaxf(mx, sS[q][k]);
        float sum = 0.0f;
        #pragma unroll
        for (int k = 0; k < SEQ; k++) { float e = expf(sS[q][k] - mx); sS[q][k] = e; sum += e; }
        const float inv = 1.0f / sum;
        #pragma unroll
        for (int k = 0; k < SEQ; k++) sS[q][k] *= inv;
    }
    __syncthreads();

    for (int i = tid; i < SEQ * HSZ; i += 128) {
        const int q = i >> 6, d = i & 63;
        float acc = 0.0f;
        #pragma unroll
        for (int k = 0; k < SEQ; k++) acc += sS[q][k] * sJv[k][d];
        outX[((size_t)b * SEQ + q) * CH + (size_t)h * HSZ + d] = f2tf32(acc);
    }
}

// ---------------------------------------------------------------------------
// Host entry
// ---------------------------------------------------------------------------
extern "C" void kernel_launch(void* const* d_in, const int* in_sizes, int n_in,
                              void* d_out, int out_size) {
    const float* joint_feature    = (const float*)d_in[0];
    const float* relation_feature = (const float*)d_in[1];
    const float* W_Jqkv  = (const float*)d_in[2];
    const float* W_Iqk   = (const float*)d_in[3];
    const float* W_Iconv = (const float*)d_in[4];
    const float* W_proj  = (const float*)d_in[5];
    const float* b_proj  = (const float*)d_in[6];
    const float* g_attn1 = (const float*)d_in[7];
    const float* b_attn1 = (const float*)d_in[8];
    const float* g_attn2 = (const float*)d_in[9];
    const float* b_attn2 = (const float*)d_in[10];
    const float* g_jln   = (const float*)d_in[11];
    const float* b_jln   = (const float*)d_in[12];
    const float* W_fc1   = (const float*)d_in[13];
    const float* b_fc1   = (const float*)d_in[14];
    const float* W_fc2   = (const float*)d_in[15];
    const float* b_fc2   = (const float*)d_in[16];
    float* out = (float*)d_out;

    float *xj, *xi, *Jq, *Iq, *ax, *jt, *yn, *hm;
    cudaGetSymbolAddress((void**)&xj, g_xj);
    cudaGetSymbolAddress((void**)&xi, g_xi);
    cudaGetSymbolAddress((void**)&Jq, g_Jqkv);
    cudaGetSymbolAddress((void**)&Iq, g_Iqkv);
    cudaGetSymbolAddress((void**)&ax, g_attnX);
    cudaGetSymbolAddress((void**)&jt, g_joint);
    cudaGetSymbolAddress((void**)&yn, g_ynorm);
    cudaGetSymbolAddress((void**)&hm, g_hmid);

    cudaFuncSetAttribute(gemm_tf32<0>, cudaFuncAttributeMaxDynamicSharedMemorySize, GEMM_SMEM);
    cudaFuncSetAttribute(gemm_tf32<1>, cudaFuncAttributeMaxDynamicSharedMemorySize, GEMM_SMEM);
    cudaFuncSetAttribute(gemm_tf32<2>, cudaFuncAttributeMaxDynamicSharedMemorySize, GEMM_SMEM);

    // 1) LN both streams (outputs tf32-prerounded)
    ln_kernel<<<MROWS, 256>>>(joint_feature,    g_attn1, b_attn1, xj);
    ln_kernel<<<MROWS, 256>>>(relation_feature, g_attn2, b_attn2, xi);

    // 2) QKV projections
    {
        dim3 grid(3 * CH / BN, MROWS / BM);
        gemm_tf32<0><<<grid, 256, GEMM_SMEM>>>(xj, W_Jqkv, Jq, 3 * CH, CH, nullptr, nullptr);
        gemm_tf32<0><<<grid, 256, GEMM_SMEM>>>(xi, W_Iqk,  Iq, 3 * CH, CH, nullptr, nullptr);
    }

    // 3) Attention (output tf32-prerounded)
    attn_kernel<<<BATCH * NH, 128>>>(Jq, Iq, W_Iconv, ax);

    // 4) proj + bias + residual -> joint (exact fp32 out)
    {
        dim3 grid(CH / BN, MROWS / BM);
        gemm_tf32<1><<<grid, 256, GEMM_SMEM>>>(ax, W_proj, jt, CH, CH, b_proj, joint_feature);
    }

    // 5) LN(joint) (output tf32-prerounded)
    ln_kernel<<<MROWS, 256>>>(jt, g_jln, b_jln, yn);

    // 6) fc1 + bias + GELU (output tf32-prerounded)
    {
        dim3 grid((CH / 2) / BN, MROWS / BM);
        gemm_tf32<2><<<grid, 256, GEMM_SMEM>>>(yn, W_fc1, hm, CH / 2, CH, b_fc1, nullptr);
    }

    // 7) fc2 + bias + residual(joint) -> out (exact fp32 out)
    {
        dim3 grid(CH / BN, MROWS / BM);
        gemm_tf32<1><<<grid, 256, GEMM_SMEM>>>(hm, W_fc2, out, CH, CH / 2, b_fc2, jt);
    }
}

// round 14
// speedup vs baseline: 1.2693x; 1.0735x over previous
#include <cuda_runtime.h>
#include <math.h>
#include <stdint.h>

// ---------------------------------------------------------------------------
// Problem constants
// ---------------------------------------------------------------------------
#define BATCH 2048
#define SEQ   15
#define CH    1024
#define NH    16
#define HSZ   64
#define MROWS (BATCH * SEQ)          // 30720
#define SCALE 0.125f
#define LN_EPS 1e-5f

// ---------------------------------------------------------------------------
// Scratch (static __device__ — no allocations allowed)
// ---------------------------------------------------------------------------
__device__ float g_xj   [(size_t)MROWS * CH];
__device__ float g_xi   [(size_t)MROWS * CH];
__device__ float g_Jqkv [(size_t)MROWS * 3 * CH];
__device__ float g_Iqkv [(size_t)MROWS * 3 * CH];
__device__ float g_attnX[(size_t)MROWS * CH];
__device__ float g_joint[(size_t)MROWS * CH];
__device__ float g_ynorm[(size_t)MROWS * CH];
__device__ float g_hmid [(size_t)MROWS * (CH / 2)];

// ---------------------------------------------------------------------------
// Helpers
// ---------------------------------------------------------------------------
__device__ __forceinline__ float f2tf32(float x) {
    unsigned u;
    asm("cvt.rna.tf32.f32 %0, %1;" : "=r"(u) : "f"(x));
    return __uint_as_float(u);
}
__device__ __forceinline__ float4 f2tf32_4(float4 v) {
    v.x = f2tf32(v.x); v.y = f2tf32(v.y); v.z = f2tf32(v.z); v.w = f2tf32(v.w);
    return v;
}
__device__ __forceinline__ void mma_tf32(float* c, const unsigned* a, const unsigned* b) {
    asm volatile(
        "mma.sync.aligned.m16n8k8.row.col.f32.tf32.tf32.f32 "
        "{%0,%1,%2,%3}, {%4,%5,%6,%7}, {%8,%9}, {%0,%1,%2,%3};\n"
        : "+f"(c[0]), "+f"(c[1]), "+f"(c[2]), "+f"(c[3])
        : "r"(a[0]), "r"(a[1]), "r"(a[2]), "r"(a[3]), "r"(b[0]), "r"(b[1]));
}
__device__ __forceinline__ unsigned smem_addr_u32(const void* p) {
    return (unsigned)__cvta_generic_to_shared(p);
}
__device__ __forceinline__ void cp_async16(unsigned s, const void* g) {
    asm volatile("cp.async.cg.shared.global [%0], [%1], 16;" :: "r"(s), "l"(g) : "memory");
}
__device__ __forceinline__ void cp_commit() {
    asm volatile("cp.async.commit_group;" ::: "memory");
}
template <int N>
__device__ __forceinline__ void cp_wait() {
    asm volatile("cp.async.wait_group %0;" :: "n"(N) : "memory");
}

// ---------------------------------------------------------------------------
// LayerNorm: one block (256 thr) per row of 1024. Output pre-rounded to tf32.
// ---------------------------------------------------------------------------
__global__ void ln_kernel(const float* __restrict__ x,
                          const float* __restrict__ g,
                          const float* __restrict__ b,
                          float* __restrict__ out) {
    const int row = blockIdx.x;
    const int t = threadIdx.x;
    const float4* xr = (const float4*)(x + (size_t)row * CH);
    float4 v = xr[t];
    float s1 = v.x + v.y + v.z + v.w;
    float s2 = v.x * v.x + v.y * v.y + v.z * v.z + v.w * v.w;
    #pragma unroll
    for (int o = 16; o; o >>= 1) {
        s1 += __shfl_xor_sync(0xffffffffu, s1, o);
        s2 += __shfl_xor_sync(0xffffffffu, s2, o);
    }
    __shared__ float w1[8], w2[8];
    if ((t & 31) == 0) { w1[t >> 5] = s1; w2[t >> 5] = s2; }
    __syncthreads();
    if (t < 32) {
        s1 = (t < 8) ? w1[t] : 0.0f;
        s2 = (t < 8) ? w2[t] : 0.0f;
        #pragma unroll
        for (int o = 4; o; o >>= 1) {
            s1 += __shfl_xor_sync(0xffffffffu, s1, o);
            s2 += __shfl_xor_sync(0xffffffffu, s2, o);
        }
        if (t == 0) { w1[0] = s1; w2[0] = s2; }
    }
    __syncthreads();
    const float m = w1[0] * (1.0f / CH);
    const float var = w2[0] * (1.0f / CH) - m * m;
    const float r = rsqrtf(var + LN_EPS);
    float4 gv = ((const float4*)g)[t];
    float4 bv = ((const float4*)b)[t];
    float4 o;
    o.x = (v.x - m) * r * gv.x + bv.x;
    o.y = (v.y - m) * r * gv.y + bv.y;
    o.z = (v.z - m) * r * gv.z + bv.z;
    o.w = (v.w - m) * r * gv.w + bv.w;
    ((float4*)(out + (size_t)row * CH))[t] = f2tf32_4(o);
}

// ---------------------------------------------------------------------------
// tf32 GEMM: C[M x Ncols] = A[M x K] * B[K x Ncols] (+epilogue)
// 128x128x32 blocktile, 3-stage cp.async pipeline, ONE sync per k-iter.
// 256 threads, 2x4 warps; warp tile 64x32; A/B pre-rounded to tf32.
// EPI: 0 = plain, 1 = +bias +resid, 2 = +bias +exact GELU (tf32 out)
// ---------------------------------------------------------------------------
#define BM 128
#define BN 128
#define BK 32
#define ASTRIDE (BK + 4)     // 36: frag addr = g*36+t -> g*4+t mod 32, distinct
#define BSTRIDE (BN + 8)     // 136: frag addr = t*136+g -> t*8+g mod 32, distinct
#define A_STAGE_F (BM * ASTRIDE)                // 4608 floats
#define STAGE_F (A_STAGE_F + BK * BSTRIDE)      // 4608 + 4352 = 8960 floats
#define NSTAGE 3
#define GEMM_SMEM (NSTAGE * STAGE_F * 4)        // 107520 bytes

template <int EPI>
__global__ __launch_bounds__(256, 2)
void gemm_tf32(const float* __restrict__ A, const float* __restrict__ B,
               float* __restrict__ C, int Ncols, int K,
               const float* __restrict__ bias, const float* __restrict__ resid) {
    extern __shared__ float smem[];

    const int tid  = threadIdx.x;
    const int warp = tid >> 5;
    const int lane = tid & 31;
    const int g = lane >> 2;          // 0..7
    const int t = lane & 3;           // 0..3
    const int wm = (warp >> 2) * 64;
    const int wn = (warp & 3) * 32;

    const int bm = blockIdx.y * BM;
    const int bn = blockIdx.x * BN;

    const float* Abase = A + (size_t)bm * K;
    const float* Bbase = B + bn;

    float acc[4][4][4];
    #pragma unroll
    for (int i = 0; i < 4; i++)
        #pragma unroll
        for (int j = 0; j < 4; j++)
            #pragma unroll
            for (int e = 0; e < 4; e++) acc[i][j][e] = 0.0f;

    const int nkt = K / BK;

    // A tile: 128 rows x 32 floats = 1024 16B-chunks; chunk c: row c>>3, col (c&7)*4
    // B tile:  32 rows x 128 floats = 1024 chunks;     chunk c: row c>>5, col (c&31)*4
    // 256 threads x 4 chunks each (2 A + 2 B slots per thread x 2)
    const int a_r0 = tid >> 3,          a_c0 = (tid & 7) << 2;
    const int a_r1 = (tid + 256) >> 3,  a_c1 = ((tid + 256) & 7) << 2;
    const int a_r2 = (tid + 512) >> 3,  a_c2 = ((tid + 512) & 7) << 2;
    const int a_r3 = (tid + 768) >> 3,  a_c3 = ((tid + 768) & 7) << 2;
    const int b_r0 = tid >> 5,          b_c0 = (tid & 31) << 2;
    const int b_r1 = (tid + 256) >> 5,  b_c1 = ((tid + 256) & 31) << 2;
    const int b_r2 = (tid + 512) >> 5,  b_c2 = ((tid + 512) & 31) << 2;
    const int b_r3 = (tid + 768) >> 5,  b_c3 = ((tid + 768) & 31) << 2;

    auto load_stage = [&](int slot, int kt) {
        float* sA = smem + slot * STAGE_F;
        float* sB = sA + A_STAGE_F;
        const int kf = kt * BK;
        cp_async16(smem_addr_u32(sA + a_r0 * ASTRIDE + a_c0), Abase + (size_t)a_r0 * K + kf + a_c0);
        cp_async16(smem_addr_u32(sA + a_r1 * ASTRIDE + a_c1), Abase + (size_t)a_r1 * K + kf + a_c1);
        cp_async16(smem_addr_u32(sA + a_r2 * ASTRIDE + a_c2), Abase + (size_t)a_r2 * K + kf + a_c2);
        cp_async16(smem_addr_u32(sA + a_r3 * ASTRIDE + a_c3), Abase + (size_t)a_r3 * K + kf + a_c3);
        cp_async16(smem_addr_u32(sB + b_r0 * BSTRIDE + b_c0), Bbase + (size_t)(kf + b_r0) * Ncols + b_c0);
        cp_async16(smem_addr_u32(sB + b_r1 * BSTRIDE + b_c1), Bbase + (size_t)(kf + b_r1) * Ncols + b_c1);
        cp_async16(smem_addr_u32(sB + b_r2 * BSTRIDE + b_c2), Bbase + (size_t)(kf + b_r2) * Ncols + b_c2);
        cp_async16(smem_addr_u32(sB + b_r3 * BSTRIDE + b_c3), Bbase + (size_t)(kf + b_r3) * Ncols + b_c3);
    };

    // prologue: slots 0 and 1
    load_stage(0, 0); cp_commit();
    load_stage(1, 1); cp_commit();

    int slot = 0;
    for (int kt = 0; kt < nkt; kt++) {
        cp_wait<1>();            // group kt complete (group kt+1 may be pending)
        __syncthreads();         // all warps done with slot consumed at kt-1

        // prefetch kt+2 into the slot consumed at kt-1 (overlaps with compute)
        if (kt + 2 < nkt) {
            int ps = slot + 2; if (ps >= NSTAGE) ps -= NSTAGE;
            load_stage(ps, kt + 2);
        }
        cp_commit();             // always commit (empty group ok) to keep counts aligned

        const float* sA = smem + slot * STAGE_F;
        const float* sB = sA + A_STAGE_F;

        #pragma unroll
        for (int ks = 0; ks < 4; ks++) {
            const int k0 = ks * 8;
            unsigned af[4][4], bf[4][2];
            #pragma unroll
            for (int mi = 0; mi < 4; mi++) {
                const int r = wm + mi * 16 + g;
                af[mi][0] = __float_as_uint(sA[(r    ) * ASTRIDE + k0 + t]);
                af[mi][1] = __float_as_uint(sA[(r + 8) * ASTRIDE + k0 + t]);
                af[mi][2] = __float_as_uint(sA[(r    ) * ASTRIDE + k0 + t + 4]);
                af[mi][3] = __float_as_uint(sA[(r + 8) * ASTRIDE + k0 + t + 4]);
            }
            #pragma unroll
            for (int ni = 0; ni < 4; ni++) {
                const int c = wn + ni * 8 + g;
                bf[ni][0] = __float_as_uint(sB[(k0 + t    ) * BSTRIDE + c]);
                bf[ni][1] = __float_as_uint(sB[(k0 + t + 4) * BSTRIDE + c]);
            }
            #pragma unroll
            for (int mi = 0; mi < 4; mi++)
                #pragma unroll
                for (int ni = 0; ni < 4; ni++)
                    mma_tf32(acc[mi][ni], af[mi], bf[ni]);
        }

        if (++slot == NSTAGE) slot = 0;
    }

    // epilogue
    #pragma unroll
    for (int mi = 0; mi < 4; mi++) {
        #pragma unroll
        for (int ni = 0; ni < 4; ni++) {
            const int r0 = bm + wm + mi * 16 + g;
            const int c0 = bn + wn + ni * 8 + t * 2;
            float v[4] = {acc[mi][ni][0], acc[mi][ni][1], acc[mi][ni][2], acc[mi][ni][3]};
            const int rr[4] = {r0, r0, r0 + 8, r0 + 8};
            const int cc[4] = {c0, c0 + 1, c0, c0 + 1};
            if (EPI != 0) {
                #pragma unroll
                for (int e = 0; e < 4; e++) {
                    v[e] += bias[cc[e]];
                    if (EPI == 1) v[e] += resid[(size_t)rr[e] * Ncols + cc[e]];
                    if (EPI == 2) {
                        v[e] = 0.5f * v[e] * (1.0f + erff(v[e] * 0.70710678118654752f));
                        v[e] = f2tf32(v[e]);   // hm feeds fc2 as A-operand
                    }
                }
            }
            float2 lo = make_float2(v[0], v[1]);
            float2 hi = make_float2(v[2], v[3]);
            *(float2*)&C[(size_t)r0       * Ncols + c0] = lo;
            *(float2*)&C[(size_t)(r0 + 8) * Ncols + c0] = hi;
        }
    }
}

// ---------------------------------------------------------------------------
// Attention: one block (128 thr) per (batch, head). Output tf32-prerounded.
// ---------------------------------------------------------------------------
__global__ __launch_bounds__(128)
void attn_kernel(const float* __restrict__ Jqkv, const float* __restrict__ Iqkv,
                 const float* __restrict__ Wc, float* __restrict__ outX) {
    const int bh = blockIdx.x;
    const int b = bh >> 4;
    const int h = bh & 15;
    const int tid = threadIdx.x;

    __shared__ float sJq[SEQ][HSZ + 1], sJk[SEQ][HSZ + 1], sJv[SEQ][HSZ + 1];
    __shared__ float sIq[SEQ][HSZ + 1], sIk[SEQ][HSZ + 1], sIv[SEQ][HSZ + 1];
    __shared__ float sW[HSZ][SEQ];
    __shared__ float sS[SEQ][SEQ + 1];

    const size_t base = (size_t)b * SEQ * (3 * CH) + (size_t)h * HSZ;
    for (int i = tid; i < SEQ * HSZ; i += 128) {
        const int n = i >> 6, d = i & 63;
        const float* jp = Jqkv + base + (size_t)n * (3 * CH) + d;
        sJq[n][d] = jp[0];
        sJk[n][d] = jp[CH];
        sJv[n][d] = jp[2 * CH];
        const float* ip = Iqkv + base + (size_t)n * (3 * CH) + d;
        sIq[n][d] = ip[0];
        sIk[n][d] = ip[CH];
        sIv[n][d] = ip[2 * CH];
    }
    for (int i = tid; i < HSZ * SEQ; i += 128) sW[i / SEQ][i % SEQ] = Wc[i];
    __syncthreads();

    for (int i = tid; i < SEQ * SEQ; i += 128) {
        const int q = i / SEQ, k = i % SEQ;
        float acc = 0.0f, accl = 0.0f;
        #pragma unroll
        for (int d = 0; d < HSZ; d++) {
            acc  += sJq[q][d] * sJk[k][d] + sIq[q][d] * sIk[k][d];
            accl += sIv[q][d] * sW[d][k];
        }
        sS[q][k] = (acc + accl) * SCALE;
    }
    __syncthreads();

    if (tid < SEQ) {
        const int q = tid;
        float mx = -1e30f;
        #pragma unroll
        for (int k = 0; k < SEQ; k++) mx = fmaxf(mx, sS[q][k]);
        float sum = 0.0f;
        #pragma unroll
        for (int k = 0; k < SEQ; k++) { float e = expf(sS[q][k] - mx); sS[q][k] = e; sum += e; }
        const float inv = 1.0f / sum;
        #pragma unroll
        for (int k = 0; k < SEQ; k++) sS[q][k] *= inv;
    }
    __syncthreads();

    for (int i = tid; i < SEQ * HSZ; i += 128) {
        const int q = i >> 6, d = i & 63;
        float acc = 0.0f;
        #pragma unroll
        for (int k = 0; k < SEQ; k++) acc += sS[q][k] * sJv[k][d];
        outX[((size_t)b * SEQ + q) * CH + (size_t)h * HSZ + d] = f2tf32(acc);
    }
}

// ---------------------------------------------------------------------------
// Host entry
// ---------------------------------------------------------------------------
extern "C" void kernel_launch(void* const* d_in, const int* in_sizes, int n_in,
                              void* d_out, int out_size) {
    const float* joint_feature    = (const float*)d_in[0];
    const float* relation_feature = (const float*)d_in[1];
    const float* W_Jqkv  = (const float*)d_in[2];
    const float* W_Iqk   = (const float*)d_in[3];
    const float* W_Iconv = (const float*)d_in[4];
    const float* W_proj  = (const float*)d_in[5];
    const float* b_proj  = (const float*)d_in[6];
    const float* g_attn1 = (const float*)d_in[7];
    const float* b_attn1 = (const float*)d_in[8];
    const float* g_attn2 = (const float*)d_in[9];
    const float* b_attn2 = (const float*)d_in[10];
    const float* g_jln   = (const float*)d_in[11];
    const float* b_jln   = (const float*)d_in[12];
    const float* W_fc1   = (const float*)d_in[13];
    const float* b_fc1   = (const float*)d_in[14];
    const float* W_fc2   = (const float*)d_in[15];
    const float* b_fc2   = (const float*)d_in[16];
    float* out = (float*)d_out;

    float *xj, *xi, *Jq, *Iq, *ax, *jt, *yn, *hm;
    cudaGetSymbolAddress((void**)&xj, g_xj);
    cudaGetSymbolAddress((void**)&xi, g_xi);
    cudaGetSymbolAddress((void**)&Jq, g_Jqkv);
    cudaGetSymbolAddress((void**)&Iq, g_Iqkv);
    cudaGetSymbolAddress((void**)&ax, g_attnX);
    cudaGetSymbolAddress((void**)&jt, g_joint);
    cudaGetSymbolAddress((void**)&yn, g_ynorm);
    cudaGetSymbolAddress((void**)&hm, g_hmid);

    cudaFuncSetAttribute(gemm_tf32<0>, cudaFuncAttributeMaxDynamicSharedMemorySize, GEMM_SMEM);
    cudaFuncSetAttribute(gemm_tf32<1>, cudaFuncAttributeMaxDynamicSharedMemorySize, GEMM_SMEM);
    cudaFuncSetAttribute(gemm_tf32<2>, cudaFuncAttributeMaxDynamicSharedMemorySize, GEMM_SMEM);

    // 1) LN both streams (tf32-prerounded outputs)
    ln_kernel<<<MROWS, 256>>>(joint_feature,    g_attn1, b_attn1, xj);
    ln_kernel<<<MROWS, 256>>>(relation_feature, g_attn2, b_attn2, xi);

    // 2) QKV projections
    {
        dim3 grid(3 * CH / BN, MROWS / BM);
        gemm_tf32<0><<<grid, 256, GEMM_SMEM>>>(xj, W_Jqkv, Jq, 3 * CH, CH, nullptr, nullptr);
        gemm_tf32<0><<<grid, 256, GEMM_SMEM>>>(xi, W_Iqk,  Iq, 3 * CH, CH, nullptr, nullptr);
    }

    // 3) Attention (tf32-prerounded output)
    attn_kernel<<<BATCH * NH, 128>>>(Jq, Iq, W_Iconv, ax);

    // 4) proj + bias + residual -> joint (exact fp32)
    {
        dim3 grid(CH / BN, MROWS / BM);
        gemm_tf32<1><<<grid, 256, GEMM_SMEM>>>(ax, W_proj, jt, CH, CH, b_proj, joint_feature);
    }

    // 5) LN(joint) (tf32-prerounded output)
    ln_kernel<<<MROWS, 256>>>(jt, g_jln, b_jln, yn);

    // 6) fc1 + bias + GELU (tf32-prerounded output)
    {
        dim3 grid((CH / 2) / BN, MROWS / BM);
        gemm_tf32<2><<<grid, 256, GEMM_SMEM>>>(yn, W_fc1, hm, CH / 2, CH, b_fc1, nullptr);
    }

    // 7) fc2 + bias + residual(joint) -> out (exact fp32)
    {
        dim3 grid(CH / BN, MROWS / BM);
        gemm_tf32<1><<<grid, 256, GEMM_SMEM>>>(hm, W_fc2, out, CH, CH / 2, b_fc2, jt);
    }
}